// round 12
// baseline (speedup 1.0000x reference)
#include <cuda_runtime.h>
#include <cuda_bf16.h>
#include <cstdint>

#define BB 4
#define TE 512
#define TD 256
#define HE 128
#define HD 256
#define TT 4

// ---- scratch (device globals; no allocation allowed) ----
__device__ float g_TWs[BB * TE * HE];       // tanh(enc @ W_a)  [B,TE,HE]
__device__ float g_TUh[BB * TD * HE];       // tanh(dec @ U_a)  [B,TD,HE]

__device__ __forceinline__ float fast_tanh(float x) {
    float y;
    asm("tanh.approx.f32 %0, %1;" : "=f"(y) : "f"(x));
    return y;
}
__device__ __forceinline__ float fast_rcp(float x) {
    float r;
    asm("rcp.approx.ftz.f32 %0, %1;" : "=f"(r) : "f"(x));
    return r;
}

// ================= Prep kernel: TUh = tanh(dec@U), TWs = tanh(enc@W) ========
__global__ __launch_bounds__(128) void prep_kernel(
    const float* __restrict__ dec, const float* __restrict__ U,
    const float* __restrict__ enc, const float* __restrict__ W)
{
    __shared__ float sbuf[1024];                 // 4 KB
    int tid = threadIdx.x;

    if (blockIdx.x < 256) {
        // ---- Uh: rows = B*TD, 4 per block ----
        int blk = blockIdx.x;
        int b  = blk >> 6;
        int t0 = (blk & 63) * 4;
        const float4* drow = reinterpret_cast<const float4*>(dec + ((size_t)b * TD + t0) * HD);
        float4* sb4 = reinterpret_cast<float4*>(sbuf);
#pragma unroll
        for (int i = 0; i < 2; i++) sb4[tid + 128 * i] = drow[tid + 128 * i];
        __syncthreads();

        float a0 = 0.f, a1 = 0.f, a2 = 0.f, a3 = 0.f;
#pragma unroll 4
        for (int d = 0; d < HD; d += 4) {
            float u0 = U[(d + 0) * HE + tid];
            float u1 = U[(d + 1) * HE + tid];
            float u2 = U[(d + 2) * HE + tid];
            float u3 = U[(d + 3) * HE + tid];
#pragma unroll
            for (int j = 0; j < 4; j++) {
                float uj = (j == 0) ? u0 : (j == 1) ? u1 : (j == 2) ? u2 : u3;
                a0 = fmaf(sbuf[0 * HD + d + j], uj, a0);
                a1 = fmaf(sbuf[1 * HD + d + j], uj, a1);
                a2 = fmaf(sbuf[2 * HD + d + j], uj, a2);
                a3 = fmaf(sbuf[3 * HD + d + j], uj, a3);
            }
        }
        size_t base = ((size_t)(b * TD + t0)) * HE + tid;
        g_TUh[base + 0 * HE] = fast_tanh(a0);
        g_TUh[base + 1 * HE] = fast_tanh(a1);
        g_TUh[base + 2 * HE] = fast_tanh(a2);
        g_TUh[base + 3 * HE] = fast_tanh(a3);
    } else {
        // ---- Ws: rows = B*TE, 8 per block ----
        int blk = blockIdx.x - 256;
        int b  = blk >> 6;
        int s0 = (blk & 63) * 8;
        const float4* erow = reinterpret_cast<const float4*>(enc + ((size_t)b * TE + s0) * HE);
        float4* sb4 = reinterpret_cast<float4*>(sbuf);
#pragma unroll
        for (int i = 0; i < 2; i++) sb4[tid + 128 * i] = erow[tid + 128 * i];
        __syncthreads();

        float acc[8];
#pragma unroll
        for (int r = 0; r < 8; r++) acc[r] = 0.f;
#pragma unroll 2
        for (int k = 0; k < HE; k += 4) {
            float w0 = W[(k + 0) * HE + tid];
            float w1 = W[(k + 1) * HE + tid];
            float w2 = W[(k + 2) * HE + tid];
            float w3 = W[(k + 3) * HE + tid];
#pragma unroll
            for (int r = 0; r < 8; r++) {
                float aa = acc[r];
                aa = fmaf(sbuf[r * HE + k + 0], w0, aa);
                aa = fmaf(sbuf[r * HE + k + 1], w1, aa);
                aa = fmaf(sbuf[r * HE + k + 2], w2, aa);
                aa = fmaf(sbuf[r * HE + k + 3], w3, aa);
                acc[r] = aa;
            }
        }
        size_t base = ((size_t)(b * TE + s0)) * HE + tid;
#pragma unroll
        for (int r = 0; r < 8; r++) g_TWs[base + (size_t)r * HE] = fast_tanh(acc[r]);
    }
}

// ========== Fused score/softmax/context, tanh-addition identity ==========
// One CTA per (b, tile of TT=4 decoder steps). 512 threads = 16 warps.
// Thread owns encoder position s = tid.  tanh(ws+uh) = (tw+tu)/(1+tw*tu).
__global__ __launch_bounds__(512) void score_ctx_kernel(
    const float* __restrict__ enc,
    const float* __restrict__ Va,
    float* __restrict__ c_out,   // [B,TD,HE]
    float* __restrict__ e_out)   // [B,TD,TE]
{
    __shared__ float s_tu[TT * HE];              // 2 KB
    __shared__ float s_v[HE];                    // 0.5 KB
    __shared__ float s_scores[TT * TE];          // 8 KB
    __shared__ float s_ctx[4][TT * HE];          // 8 KB

    int blk = blockIdx.x;
    int b  = blk / (TD / TT);
    int t0 = (blk % (TD / TT)) * TT;
    int tid  = threadIdx.x;                      // 0..511 == encoder position s
    int warp = tid >> 5;
    int lane = tid & 31;

    // stage TUh tile (512 values -> 1 per thread) + V (independent predicate!)
    s_tu[tid & 511] = g_TUh[((size_t)(b * TD + t0)) * HE + tid];
    if (tid < HE) s_v[tid] = Va[tid];
    __syncthreads();

    const float4* tu4  = reinterpret_cast<const float4*>(s_tu);
    const float4* v4p  = reinterpret_cast<const float4*>(s_v);

    // ---- Phase 1: scores via identity. Per eval: 4 fma-pipe + 1 RCP. ----
    {
        const float4* wrow = reinterpret_cast<const float4*>(
            g_TWs + ((size_t)b * TE + tid) * HE);
        float acc[TT];
#pragma unroll
        for (int t = 0; t < TT; t++) acc[t] = 0.f;

#pragma unroll 8
        for (int q = 0; q < HE / 4; q++) {
            float4 w = wrow[q];
            float4 v = v4p[q];
#pragma unroll
            for (int t = 0; t < TT; t++) {
                float4 u = tu4[t * (HE / 4) + q];
                float a = acc[t];
                a = fmaf(v.x * (w.x + u.x), fast_rcp(fmaf(w.x, u.x, 1.0f)), a);
                a = fmaf(v.y * (w.y + u.y), fast_rcp(fmaf(w.y, u.y, 1.0f)), a);
                a = fmaf(v.z * (w.z + u.z), fast_rcp(fmaf(w.z, u.z, 1.0f)), a);
                a = fmaf(v.w * (w.w + u.w), fast_rcp(fmaf(w.w, u.w, 1.0f)), a);
                acc[t] = a;
            }
        }
#pragma unroll
        for (int t = 0; t < TT; t++)
            s_scores[t * TE + tid] = acc[t];
    }
    __syncthreads();

    // ---- Phase 2: softmax per decoder step (warps 0..3) ----
    if (warp < TT) {
        int t = warp;
        float* sc = s_scores + t * TE;
        float m = -1e30f;
        for (int s = lane; s < TE; s += 32) m = fmaxf(m, sc[s]);
#pragma unroll
        for (int o = 16; o > 0; o >>= 1)
            m = fmaxf(m, __shfl_xor_sync(0xFFFFFFFFu, m, o));
        float sum = 0.f;
        for (int s = lane; s < TE; s += 32) {
            float ex = __expf(sc[s] - m);
            sc[s] = ex;
            sum += ex;
        }
#pragma unroll
        for (int o = 16; o > 0; o >>= 1)
            sum += __shfl_xor_sync(0xFFFFFFFFu, sum, o);
        float inv = 1.0f / sum;
        float* eo = e_out + ((size_t)(b * TD + t0 + t)) * TE;
        for (int s = lane; s < TE; s += 32) {
            float w = sc[s] * inv;
            sc[s] = w;
            eo[s] = w;
        }
    }
    __syncthreads();

    // ---- Phase 3: context. 4 groups of 128 threads split the s-range. ----
    {
        int g  = tid >> 7;              // 0..3
        int ee = tid & 127;             // output feature
        const float* encb = enc + (size_t)b * TE * HE;
        float a0 = 0.f, a1 = 0.f, a2 = 0.f, a3 = 0.f;
        int sbeg = g * (TE / 4);
#pragma unroll 2
        for (int s = sbeg; s < sbeg + TE / 4; s += 4) {
            float4 w0 = *reinterpret_cast<const float4*>(&s_scores[0 * TE + s]);
            float4 w1 = *reinterpret_cast<const float4*>(&s_scores[1 * TE + s]);
            float4 w2 = *reinterpret_cast<const float4*>(&s_scores[2 * TE + s]);
            float4 w3 = *reinterpret_cast<const float4*>(&s_scores[3 * TE + s]);
            float x0 = encb[(size_t)(s + 0) * HE + ee];
            float x1 = encb[(size_t)(s + 1) * HE + ee];
            float x2 = encb[(size_t)(s + 2) * HE + ee];
            float x3 = encb[(size_t)(s + 3) * HE + ee];
            a0 = fmaf(w0.x, x0, fmaf(w0.y, x1, fmaf(w0.z, x2, fmaf(w0.w, x3, a0))));
            a1 = fmaf(w1.x, x0, fmaf(w1.y, x1, fmaf(w1.z, x2, fmaf(w1.w, x3, a1))));
            a2 = fmaf(w2.x, x0, fmaf(w2.y, x1, fmaf(w2.z, x2, fmaf(w2.w, x3, a2))));
            a3 = fmaf(w3.x, x0, fmaf(w3.y, x1, fmaf(w3.z, x2, fmaf(w3.w, x3, a3))));
        }
        s_ctx[g][0 * HE + ee] = a0;
        s_ctx[g][1 * HE + ee] = a1;
        s_ctx[g][2 * HE + ee] = a2;
        s_ctx[g][3 * HE + ee] = a3;
    }
    __syncthreads();

    // combine: 512 threads -> 512 outputs (TT*HE)
    {
        float r = s_ctx[0][tid] + s_ctx[1][tid] + s_ctx[2][tid] + s_ctx[3][tid];
        int tt = tid >> 7;
        int ee = tid & 127;
        c_out[((size_t)(b * TD + t0 + tt)) * HE + ee] = r;
    }
}

extern "C" void kernel_launch(void* const* d_in, const int* in_sizes, int n_in,
                              void* d_out, int out_size) {
    const float* enc = (const float*)d_in[0];   // [B,TE,HE]
    const float* dec = (const float*)d_in[1];   // [B,TD,HD]
    const float* Wa  = (const float*)d_in[2];   // [HE,HE]
    const float* Ua  = (const float*)d_in[3];   // [HD,HE]
    const float* Va  = (const float*)d_in[4];   // [HE,1]

    float* out   = (float*)d_out;
    float* c_out = out;                          // [B,TD,HE]
    float* e_out = out + (size_t)BB * TD * HE;   // [B,TD,TE]

    prep_kernel<<<512, 128>>>(dec, Ua, enc, Wa);
    score_ctx_kernel<<<BB * (TD / TT), 512>>>(enc, Va, c_out, e_out);
}

// round 13
// speedup vs baseline: 1.0799x; 1.0799x over previous
#include <cuda_runtime.h>
#include <cuda_bf16.h>
#include <cstdint>

#define BB 4
#define TE 512
#define TD 256
#define HE 128
#define HD 256
#define TT 4

// ---- scratch (device globals; no allocation allowed) ----
__device__ float g_TWsT[BB * HE * TE];      // tanh(enc @ W_a) TRANSPOSED [B,HE,TE]
__device__ float g_TUh[BB * TD * HE];       // tanh(dec @ U_a)            [B,TD,HE]

__device__ __forceinline__ float fast_tanh(float x) {
    float y;
    asm("tanh.approx.f32 %0, %1;" : "=f"(y) : "f"(x));
    return y;
}
__device__ __forceinline__ float fast_rcp(float x) {
    float r;
    asm("rcp.approx.ftz.f32 %0, %1;" : "=f"(r) : "f"(x));
    return r;
}

// ================= Prep kernel: TUh = tanh(dec@U), TWsT = tanh(enc@W)^T =====
__global__ __launch_bounds__(128) void prep_kernel(
    const float* __restrict__ dec, const float* __restrict__ U,
    const float* __restrict__ enc, const float* __restrict__ W)
{
    __shared__ float sbuf[1024];                 // 4 KB
    int tid = threadIdx.x;

    if (blockIdx.x < 256) {
        // ---- Uh: rows = B*TD, 4 per block ----
        int blk = blockIdx.x;
        int b  = blk >> 6;
        int t0 = (blk & 63) * 4;
        const float4* drow = reinterpret_cast<const float4*>(dec + ((size_t)b * TD + t0) * HD);
        float4* sb4 = reinterpret_cast<float4*>(sbuf);
#pragma unroll
        for (int i = 0; i < 2; i++) sb4[tid + 128 * i] = drow[tid + 128 * i];
        __syncthreads();

        float a0 = 0.f, a1 = 0.f, a2 = 0.f, a3 = 0.f;
#pragma unroll 4
        for (int d = 0; d < HD; d += 4) {
            float u0 = U[(d + 0) * HE + tid];
            float u1 = U[(d + 1) * HE + tid];
            float u2 = U[(d + 2) * HE + tid];
            float u3 = U[(d + 3) * HE + tid];
#pragma unroll
            for (int j = 0; j < 4; j++) {
                float uj = (j == 0) ? u0 : (j == 1) ? u1 : (j == 2) ? u2 : u3;
                a0 = fmaf(sbuf[0 * HD + d + j], uj, a0);
                a1 = fmaf(sbuf[1 * HD + d + j], uj, a1);
                a2 = fmaf(sbuf[2 * HD + d + j], uj, a2);
                a3 = fmaf(sbuf[3 * HD + d + j], uj, a3);
            }
        }
        size_t base = ((size_t)(b * TD + t0)) * HE + tid;
        g_TUh[base + 0 * HE] = fast_tanh(a0);
        g_TUh[base + 1 * HE] = fast_tanh(a1);
        g_TUh[base + 2 * HE] = fast_tanh(a2);
        g_TUh[base + 3 * HE] = fast_tanh(a3);
    } else {
        // ---- Ws: rows = B*TE, 8 per block; write TRANSPOSED [B,f,s] ----
        int blk = blockIdx.x - 256;
        int b  = blk >> 6;
        int s0 = (blk & 63) * 8;
        const float4* erow = reinterpret_cast<const float4*>(enc + ((size_t)b * TE + s0) * HE);
        float4* sb4 = reinterpret_cast<float4*>(sbuf);
#pragma unroll
        for (int i = 0; i < 2; i++) sb4[tid + 128 * i] = erow[tid + 128 * i];
        __syncthreads();

        float acc[8];
#pragma unroll
        for (int r = 0; r < 8; r++) acc[r] = 0.f;
#pragma unroll 2
        for (int k = 0; k < HE; k += 4) {
            float w0 = W[(k + 0) * HE + tid];
            float w1 = W[(k + 1) * HE + tid];
            float w2 = W[(k + 2) * HE + tid];
            float w3 = W[(k + 3) * HE + tid];
#pragma unroll
            for (int r = 0; r < 8; r++) {
                float aa = acc[r];
                aa = fmaf(sbuf[r * HE + k + 0], w0, aa);
                aa = fmaf(sbuf[r * HE + k + 1], w1, aa);
                aa = fmaf(sbuf[r * HE + k + 2], w2, aa);
                aa = fmaf(sbuf[r * HE + k + 3], w3, aa);
                acc[r] = aa;
            }
        }
        // TWsT[b][f=tid][s0+r]
        size_t base = ((size_t)b * HE + tid) * TE + s0;
#pragma unroll
        for (int r = 0; r < 8; r++) g_TWsT[base + r] = fast_tanh(acc[r]);
    }
}

// ========== Fused score/softmax/context, identity + transposed TWs ==========
// One CTA per (b, tile of TT=4 decoder steps). 512 threads = 16 warps.
// Thread owns encoder position s = tid. TWsT reads are COALESCED (lane = s).
__global__ __launch_bounds__(512) void score_ctx_kernel(
    const float* __restrict__ enc,
    const float* __restrict__ Va,
    float* __restrict__ c_out,   // [B,TD,HE]
    float* __restrict__ e_out)   // [B,TD,TE]
{
    __shared__ float s_tu[TT * HE];              // 2 KB
    __shared__ float s_v[HE];                    // 0.5 KB
    __shared__ float s_scores[TT * TE];          // 8 KB
    __shared__ float s_ctx[4][TT * HE];          // 8 KB

    int blk = blockIdx.x;
    int b  = blk / (TD / TT);
    int t0 = (blk % (TD / TT)) * TT;
    int tid  = threadIdx.x;                      // 0..511 == encoder position s
    int warp = tid >> 5;
    int lane = tid & 31;

    s_tu[tid & 511] = g_TUh[((size_t)(b * TD + t0)) * HE + tid];
    if (tid < HE) s_v[tid] = Va[tid];
    __syncthreads();

    const float4* tu4 = reinterpret_cast<const float4*>(s_tu);
    const float4* v4p = reinterpret_cast<const float4*>(s_v);

    // ---- Phase 1: scores. w loads: 4 coalesced LDG.32 per 4-feature group ----
    {
        const float* wcol = g_TWsT + (size_t)b * HE * TE + tid;   // + f*TE
        float acc[TT];
#pragma unroll
        for (int t = 0; t < TT; t++) acc[t] = 0.f;

#pragma unroll 8
        for (int q = 0; q < HE / 4; q++) {
            float wx = wcol[(4 * q + 0) * TE];
            float wy = wcol[(4 * q + 1) * TE];
            float wz = wcol[(4 * q + 2) * TE];
            float ww = wcol[(4 * q + 3) * TE];
            float4 v = v4p[q];
#pragma unroll
            for (int t = 0; t < TT; t++) {
                float4 u = tu4[t * (HE / 4) + q];
                float a = acc[t];
                a = fmaf(v.x * (wx + u.x), fast_rcp(fmaf(wx, u.x, 1.0f)), a);
                a = fmaf(v.y * (wy + u.y), fast_rcp(fmaf(wy, u.y, 1.0f)), a);
                a = fmaf(v.z * (wz + u.z), fast_rcp(fmaf(wz, u.z, 1.0f)), a);
                a = fmaf(v.w * (ww + u.w), fast_rcp(fmaf(ww, u.w, 1.0f)), a);
                acc[t] = a;
            }
        }
#pragma unroll
        for (int t = 0; t < TT; t++)
            s_scores[t * TE + tid] = acc[t];
    }
    __syncthreads();

    // ---- Phase 2: softmax per decoder step (warps 0..3) ----
    if (warp < TT) {
        int t = warp;
        float* sc = s_scores + t * TE;
        float m = -1e30f;
        for (int s = lane; s < TE; s += 32) m = fmaxf(m, sc[s]);
#pragma unroll
        for (int o = 16; o > 0; o >>= 1)
            m = fmaxf(m, __shfl_xor_sync(0xFFFFFFFFu, m, o));
        float sum = 0.f;
        for (int s = lane; s < TE; s += 32) {
            float ex = __expf(sc[s] - m);
            sc[s] = ex;
            sum += ex;
        }
#pragma unroll
        for (int o = 16; o > 0; o >>= 1)
            sum += __shfl_xor_sync(0xFFFFFFFFu, sum, o);
        float inv = 1.0f / sum;
        float* eo = e_out + ((size_t)(b * TD + t0 + t)) * TE;
        for (int s = lane; s < TE; s += 32) {
            float w = sc[s] * inv;
            sc[s] = w;
            eo[s] = w;
        }
    }
    __syncthreads();

    // ---- Phase 3: context. 4 groups of 128 threads split the s-range. ----
    {
        int g  = tid >> 7;              // 0..3
        int ee = tid & 127;             // output feature
        const float* encb = enc + (size_t)b * TE * HE;
        float a0 = 0.f, a1 = 0.f, a2 = 0.f, a3 = 0.f;
        int sbeg = g * (TE / 4);
#pragma unroll 2
        for (int s = sbeg; s < sbeg + TE / 4; s += 4) {
            float4 w0 = *reinterpret_cast<const float4*>(&s_scores[0 * TE + s]);
            float4 w1 = *reinterpret_cast<const float4*>(&s_scores[1 * TE + s]);
            float4 w2 = *reinterpret_cast<const float4*>(&s_scores[2 * TE + s]);
            float4 w3 = *reinterpret_cast<const float4*>(&s_scores[3 * TE + s]);
            float x0 = encb[(size_t)(s + 0) * HE + ee];
            float x1 = encb[(size_t)(s + 1) * HE + ee];
            float x2 = encb[(size_t)(s + 2) * HE + ee];
            float x3 = encb[(size_t)(s + 3) * HE + ee];
            a0 = fmaf(w0.x, x0, fmaf(w0.y, x1, fmaf(w0.z, x2, fmaf(w0.w, x3, a0))));
            a1 = fmaf(w1.x, x0, fmaf(w1.y, x1, fmaf(w1.z, x2, fmaf(w1.w, x3, a1))));
            a2 = fmaf(w2.x, x0, fmaf(w2.y, x1, fmaf(w2.z, x2, fmaf(w2.w, x3, a2))));
            a3 = fmaf(w3.x, x0, fmaf(w3.y, x1, fmaf(w3.z, x2, fmaf(w3.w, x3, a3))));
        }
        s_ctx[g][0 * HE + ee] = a0;
        s_ctx[g][1 * HE + ee] = a1;
        s_ctx[g][2 * HE + ee] = a2;
        s_ctx[g][3 * HE + ee] = a3;
    }
    __syncthreads();

    {
        float r = s_ctx[0][tid] + s_ctx[1][tid] + s_ctx[2][tid] + s_ctx[3][tid];
        int tt = tid >> 7;
        int ee = tid & 127;
        c_out[((size_t)(b * TD + t0 + tt)) * HE + ee] = r;
    }
}

extern "C" void kernel_launch(void* const* d_in, const int* in_sizes, int n_in,
                              void* d_out, int out_size) {
    const float* enc = (const float*)d_in[0];   // [B,TE,HE]
    const float* dec = (const float*)d_in[1];   // [B,TD,HD]
    const float* Wa  = (const float*)d_in[2];   // [HE,HE]
    const float* Ua  = (const float*)d_in[3];   // [HD,HE]
    const float* Va  = (const float*)d_in[4];   // [HE,1]

    float* out   = (float*)d_out;
    float* c_out = out;                          // [B,TD,HE]
    float* e_out = out + (size_t)BB * TD * HE;   // [B,TD,TE]

    prep_kernel<<<512, 128>>>(dec, Ua, enc, Wa);
    score_ctx_kernel<<<BB * (TD / TT), 512>>>(enc, Va, c_out, e_out);
}